// round 5
// baseline (speedup 1.0000x reference)
#include <cuda_runtime.h>
#include <cuda_bf16.h>
#include <cstdint>

// Problem constants (fixed by the dataset)
#define Bn 16384
#define Dn 2048
#define Hn 512
#define BDn ((size_t)Bn * (size_t)Dn)

// ---------------------------------------------------------------------------
// Scratch (device globals — no allocations allowed)
// ---------------------------------------------------------------------------
__device__ __align__(16) __nv_bfloat16 g_xhi[BDn];                  // 64 MB
__device__ __align__(16) __nv_bfloat16 g_xlo[BDn];                  // 64 MB
__device__ __align__(16) __nv_bfloat16 g_w1t_hi[(size_t)Hn * Dn];  // 2 MB (W1^T [n][k])
__device__ __align__(16) __nv_bfloat16 g_w1t_lo[(size_t)Hn * Dn];
__device__ float g_part[4 * Bn];    // per-nblock row partial sums
__device__ int   g_fixcnt;
__device__ int   g_fixlist[Bn];
__device__ int   g_k[Bn];
__device__ float g_l1[Bn];

// ---------------------------------------------------------------------------
// PTX helpers — base-target instructions only (compute_103-safe).
// ---------------------------------------------------------------------------
__device__ __forceinline__ uint32_t smem_u32(const void* p) {
    uint32_t a;
    asm("{ .reg .u64 t; cvta.to.shared.u64 t, %1; cvt.u32.u64 %0, t; }" : "=r"(a) : "l"(p));
    return a;
}
__device__ __forceinline__ void cp16(uint32_t s, const void* g) {
    asm volatile("cp.async.cg.shared.global [%0], [%1], 16;" :: "r"(s), "l"(g));
}
#define CP_COMMIT() asm volatile("cp.async.commit_group;" ::: "memory")
#define CP_WAIT(n)  asm volatile("cp.async.wait_group %0;" :: "n"(n) : "memory")

#define LDSM4(r, a) \
    asm volatile("ldmatrix.sync.aligned.m8n8.x4.shared.b16 {%0,%1,%2,%3}, [%4];" \
        : "=r"((r)[0]), "=r"((r)[1]), "=r"((r)[2]), "=r"((r)[3]) : "r"(a))

__device__ __forceinline__ void mma16816(float* c, const uint32_t* a,
                                         uint32_t b0, uint32_t b1) {
    asm volatile("mma.sync.aligned.m16n8k16.row.col.f32.bf16.bf16.f32 "
        "{%0,%1,%2,%3},{%4,%5,%6,%7},{%8,%9},{%0,%1,%2,%3};"
        : "+f"(c[0]), "+f"(c[1]), "+f"(c[2]), "+f"(c[3])
        : "r"(a[0]), "r"(a[1]), "r"(a[2]), "r"(a[3]), "r"(b0), "r"(b1));
}

// ---------------------------------------------------------------------------
// Kernel 1: convert x -> (hi, lo) bf16 split. Also zeroes the fixup counter.
// ---------------------------------------------------------------------------
__global__ __launch_bounds__(256)
void convert_x_kernel(const float* __restrict__ x)
{
    if (blockIdx.x == 0 && threadIdx.x == 0) g_fixcnt = 0;
    size_t i = ((size_t)blockIdx.x * 256 + threadIdx.x) * 8;
    float4 a = *(const float4*)(x + i);
    float4 b = *(const float4*)(x + i + 4);
    float v[8] = {a.x, a.y, a.z, a.w, b.x, b.y, b.z, b.w};
    __align__(16) __nv_bfloat16 h[8], l[8];
#pragma unroll
    for (int j = 0; j < 8; j++) {
        h[j] = __float2bfloat16_rn(v[j]);
        l[j] = __float2bfloat16_rn(v[j] - __bfloat162float(h[j]));
    }
    *(uint4*)(g_xhi + i) = *(uint4*)h;
    *(uint4*)(g_xlo + i) = *(uint4*)l;
}

// ---------------------------------------------------------------------------
// Kernel 2: transpose + split W1 [K,N] f32 -> W1^T [N,K] bf16 hi/lo.
// 32x32 smem tiles, block (32,8), grid (64,16).
// ---------------------------------------------------------------------------
__global__ void convert_w_kernel(const float* __restrict__ W1)
{
    __shared__ float tile[32][33];
    const int kb = blockIdx.x * 32, nb = blockIdx.y * 32;
    const int tx = threadIdx.x, ty = threadIdx.y;
#pragma unroll
    for (int i = 0; i < 32; i += 8)
        tile[ty + i][tx] = W1[(size_t)(kb + ty + i) * Hn + nb + tx];
    __syncthreads();
#pragma unroll
    for (int i = 0; i < 32; i += 8) {
        const int n = nb + ty + i, k = kb + tx;
        float v = tile[tx][ty + i];
        __nv_bfloat16 h = __float2bfloat16_rn(v);
        __nv_bfloat16 l = __float2bfloat16_rn(v - __bfloat162float(h));
        g_w1t_hi[(size_t)n * Dn + k] = h;
        g_w1t_lo[(size_t)n * Dn + k] = l;
    }
}

// ---------------------------------------------------------------------------
// Kernel 3: warp-MMA bf16 GEMM + fused epilogue partials.
// CTA 128(m) x 128(n); grid (128, 4); 8 warps = 2m x 4n, warp tile 64x32.
// K: 3 splits x 64 chunks of 32.  Smem row stride 80B (ldmatrix conflict-free).
// ---------------------------------------------------------------------------
#define STG 10240   // bytes per stage per operand (128 rows * 80B)

__global__ __launch_bounds__(256, 2)
void mma_gemm_kernel(const float* __restrict__ b1,
                     const float* __restrict__ W2)
{
    __shared__ __align__(16) char sAmem[2][STG];
    __shared__ __align__(16) char sBmem[2][STG];
    __shared__ float rs[128][4];

    const int t = threadIdx.x;
    const int w = t >> 5, lane = t & 31;
    const int mb = blockIdx.x;               // 0..127
    const int nb = blockIdx.y;               // 0..3
    const int warp_m = (w >> 2) * 64;
    const int warp_n = (w & 3) * 32;

    const uint32_t saA = smem_u32(sAmem);
    const uint32_t saB = smem_u32(sBmem);

    // split source pointers (terms: hi*Whi, hi*Wlo, lo*Whi)
    const __nv_bfloat16* Aspl[3] = {
        g_xhi + (size_t)mb * 128 * Dn, g_xhi + (size_t)mb * 128 * Dn,
        g_xlo + (size_t)mb * 128 * Dn };
    const __nv_bfloat16* Bspl[3] = {
        g_w1t_hi + (size_t)nb * 128 * Dn, g_w1t_lo + (size_t)nb * 128 * Dn,
        g_w1t_hi + (size_t)nb * 128 * Dn };

    // cp.async per-thread mapping: 512 16B-chunks per operand, 2 per thread
    const int r0 = t >> 2,        c0 = t & 3;
    const int r1 = (t + 256) >> 2;
    const uint32_t oS0 = r0 * 80 + c0 * 16;
    const uint32_t oS1 = r1 * 80 + c0 * 16;
    const size_t   eG0 = (size_t)r0 * Dn + c0 * 8;
    const size_t   eG1 = (size_t)r1 * Dn + c0 * 8;

    // ldmatrix per-thread base offsets
    const uint32_t aOff = (uint32_t)(warp_m + (lane & 7) + ((lane >> 3) & 1) * 8) * 80
                        + ((lane >> 4) & 1) * 16;
    const uint32_t bOff = (uint32_t)(warp_n + (lane & 7) + ((lane >> 4) & 1) * 8) * 80
                        + ((lane >> 3) & 1) * 16;

    float acc[4][4][4];
#pragma unroll
    for (int i = 0; i < 4; i++)
#pragma unroll
        for (int j = 0; j < 4; j++)
#pragma unroll
            for (int q = 0; q < 4; q++) acc[i][j][q] = 0.f;

    // prologue: load chunk 0
    {
        const __nv_bfloat16* Ab = Aspl[0];
        const __nv_bfloat16* Bb = Bspl[0];
        cp16(saA + oS0, Ab + eG0); cp16(saA + oS1, Ab + eG1);
        cp16(saB + oS0, Bb + eG0); cp16(saB + oS1, Bb + eG1);
        CP_COMMIT();
    }

    for (int cc = 0; cc < 192; cc++) {
        const int buf = cc & 1;
        if (cc < 191) {
            const int nc = cc + 1, s = nc >> 6, kc = nc & 63;
            const __nv_bfloat16* Ab = Aspl[s] + kc * 32;
            const __nv_bfloat16* Bb = Bspl[s] + kc * 32;
            const uint32_t so = (uint32_t)((nc & 1) * STG);
            cp16(saA + so + oS0, Ab + eG0); cp16(saA + so + oS1, Ab + eG1);
            cp16(saB + so + oS0, Bb + eG0); cp16(saB + so + oS1, Bb + eG1);
            CP_COMMIT();
            CP_WAIT(1);
        } else {
            CP_WAIT(0);
        }
        __syncthreads();

        const uint32_t sA = saA + buf * STG + aOff;
        const uint32_t sB = saB + buf * STG + bOff;
#pragma unroll
        for (int kk = 0; kk < 2; kk++) {
            uint32_t af[4][4], bf[2][4];
#pragma unroll
            for (int fm = 0; fm < 4; fm++) LDSM4(af[fm], sA + fm * (16 * 80) + kk * 32);
#pragma unroll
            for (int fp = 0; fp < 2; fp++) LDSM4(bf[fp], sB + fp * (16 * 80) + kk * 32);
#pragma unroll
            for (int fm = 0; fm < 4; fm++)
#pragma unroll
                for (int fn = 0; fn < 4; fn++)
                    mma16816(acc[fm][fn], af[fm],
                             bf[fn >> 1][(fn & 1) * 2], bf[fn >> 1][(fn & 1) * 2 + 1]);
        }
        __syncthreads();
    }

    // ---- epilogue: relu(c + b1)*W2, reduce over this CTA's 128 n-cols ----
    float biasv[8], w2v[8];
#pragma unroll
    for (int fn = 0; fn < 4; fn++)
#pragma unroll
        for (int e = 0; e < 2; e++) {
            const int colg = nb * 128 + warp_n + 8 * fn + 2 * (lane & 3) + e;
            biasv[fn * 2 + e] = __ldg(&b1[colg]);
            w2v[fn * 2 + e]   = __ldg(&W2[colg]);
        }

#pragma unroll
    for (int fm = 0; fm < 4; fm++) {
        float s0 = 0.f, s1 = 0.f;
#pragma unroll
        for (int fn = 0; fn < 4; fn++)
#pragma unroll
            for (int e = 0; e < 2; e++) {
                s0 += fmaxf(acc[fm][fn][e]     + biasv[fn * 2 + e], 0.f) * w2v[fn * 2 + e];
                s1 += fmaxf(acc[fm][fn][2 + e] + biasv[fn * 2 + e], 0.f) * w2v[fn * 2 + e];
            }
        s0 += __shfl_xor_sync(0xffffffffu, s0, 1);
        s0 += __shfl_xor_sync(0xffffffffu, s0, 2);
        s1 += __shfl_xor_sync(0xffffffffu, s1, 1);
        s1 += __shfl_xor_sync(0xffffffffu, s1, 2);
        if ((lane & 3) == 0) {
            rs[warp_m + 16 * fm + (lane >> 2)][w & 3]     = s0;
            rs[warp_m + 16 * fm + 8 + (lane >> 2)][w & 3] = s1;
        }
    }
    __syncthreads();
    if (t < 128)
        g_part[(size_t)nb * Bn + mb * 128 + t] = rs[t][0] + rs[t][1] + rs[t][2] + rs[t][3];
}

// ---------------------------------------------------------------------------
// Kernel 4: combine 4 n-block partials -> sigmoid -> sparsity, k, fixup flags.
// ---------------------------------------------------------------------------
__global__ __launch_bounds__(256)
void pred_final_kernel(const float* __restrict__ b2,
                       float* __restrict__ out_sparsity,
                       int* __restrict__ gk)
{
    const int row = blockIdx.x * 256 + threadIdx.x;
    float s = g_part[row] + g_part[Bn + row] + g_part[2 * Bn + row] + g_part[3 * Bn + row];
    float logit = s + b2[0];
    float sig = 1.f / (1.f + expf(-logit));
    float sp  = 0.05f + 0.25f * sig;
    float kf  = 2048.f * (1.f - sp);
    int k = (int)rintf(kf);
    if (k < 1) k = 1;
    out_sparsity[row] = sp;
    gk[row] = k;
    float frac = kf - floorf(kf);
    if (fabsf(frac - 0.5f) < 0.004f) {     // bf16-split error << 0.004
        int idx = atomicAdd(&g_fixcnt, 1);
        g_fixlist[idx] = row;
    }
}

// ---------------------------------------------------------------------------
// Kernel 5: exact fp32 recompute of sparsity/k for flagged boundary rows.
// ---------------------------------------------------------------------------
__global__ __launch_bounds__(512)
void fixup_kernel(const float* __restrict__ x,
                  const float* __restrict__ W1,
                  const float* __restrict__ b1,
                  const float* __restrict__ W2,
                  const float* __restrict__ b2,
                  float* __restrict__ out_sparsity,
                  int* __restrict__ gk)
{
    __shared__ float xs[Dn];
    __shared__ float rsw[16];
    const int cnt = g_fixcnt;
    const int n = threadIdx.x;
    const int lane = n & 31, w = n >> 5;

    for (int it = blockIdx.x; it < cnt; it += gridDim.x) {
        const int r = g_fixlist[it];
        const float* xr = x + (size_t)r * Dn;
        for (int k = n; k < Dn; k += 512) xs[k] = xr[k];
        __syncthreads();

        float h = 0.f;
        for (int k = 0; k < Dn; k++) h = fmaf(xs[k], W1[(size_t)k * Hn + n], h);
        float p = fmaxf(h + b1[n], 0.f) * W2[n];
#pragma unroll
        for (int o = 16; o > 0; o >>= 1) p += __shfl_down_sync(0xffffffffu, p, o);
        if (lane == 0) rsw[w] = p;
        __syncthreads();
        if (n == 0) {
            float s = 0.f;
#pragma unroll
            for (int q = 0; q < 16; q++) s += rsw[q];
            float logit = s + b2[0];
            float sig = 1.f / (1.f + expf(-logit));
            float sp  = 0.05f + 0.25f * sig;
            int k = (int)rintf(2048.f * (1.f - sp));
            if (k < 1) k = 1;
            out_sparsity[r] = sp;
            gk[r] = k;
        }
        __syncthreads();
    }
}

// ---------------------------------------------------------------------------
// Kernel 6: per-row exact k-th smallest |x| via radix select (unchanged).
// ---------------------------------------------------------------------------
__global__ __launch_bounds__(256)
void select_kernel(const float* __restrict__ x,
                   const int* __restrict__ gk,
                   float* __restrict__ out,
                   float* __restrict__ gl1)
{
    __shared__ int hist[256];
    __shared__ int warpsum[8];
    __shared__ int warpoff[8];
    __shared__ int s_bin, s_rem;
    __shared__ int scnt[8];
    __shared__ float sl1[8];

    const int r = blockIdx.x;
    const int t = threadIdx.x;
    const float* xr = x + (size_t)r * Dn;

    float    xv[8];
    unsigned kb[8];
#pragma unroll
    for (int i = 0; i < 8; i++) {
        xv[i] = xr[t + 256 * i];
        kb[i] = __float_as_uint(fabsf(xv[i]));
    }

    int kt = gk[r];
    unsigned prefix = 0, himask = 0;

#pragma unroll
    for (int p = 3; p >= 0; p--) {
        const int shift = p * 8;
        hist[t] = 0;
        __syncthreads();

#pragma unroll
        for (int i = 0; i < 8; i++) {
            unsigned key = kb[i];
            bool act = ((key & himask) == prefix);
            int bin = act ? (int)((key >> shift) & 0xFF) : -1;
            unsigned grp = __match_any_sync(0xffffffffu, bin);
            int leader = __ffs(grp) - 1;
            if (act && (t & 31) == leader) atomicAdd(&hist[bin], __popc(grp));
        }
        __syncthreads();

        int c = hist[t];
        int v = c;
        const int lane = t & 31, w = t >> 5;
#pragma unroll
        for (int o = 1; o < 32; o <<= 1) {
            int nn = __shfl_up_sync(0xffffffffu, v, o);
            if (lane >= o) v += nn;
        }
        if (lane == 31) warpsum[w] = v;
        __syncthreads();
        if (t == 0) {
            int run = 0;
#pragma unroll
            for (int q = 0; q < 8; q++) { warpoff[q] = run; run += warpsum[q]; }
        }
        __syncthreads();
        int incl = v + warpoff[w];
        int excl = incl - c;
        if (excl < kt && incl >= kt) { s_bin = t; s_rem = kt - excl; }
        __syncthreads();

        prefix |= ((unsigned)s_bin) << shift;
        kt = s_rem;
        himask |= 0xFFu << shift;
        __syncthreads();
    }

    const unsigned thr = prefix;
    int cnt = 0;
    float l1 = 0.f;
    const size_t base = (size_t)r * Dn;
#pragma unroll
    for (int i = 0; i < 8; i++) {
        bool keep = kb[i] > thr;
        size_t idx = base + (size_t)(t + 256 * i);
        out[idx]       = keep ? xv[i] : 0.f;
        out[BDn + idx] = keep ? 1.f : 0.f;
        cnt += keep ? 1 : 0;
        l1  += keep ? __uint_as_float(kb[i]) : 0.f;
    }

    const int lane = t & 31, w = t >> 5;
#pragma unroll
    for (int o = 16; o > 0; o >>= 1) {
        cnt += __shfl_down_sync(0xffffffffu, cnt, o);
        l1  += __shfl_down_sync(0xffffffffu, l1, o);
    }
    if (lane == 0) { scnt[w] = cnt; sl1[w] = l1; }
    __syncthreads();
    if (t == 0) {
        int C = 0; float L = 0.f;
#pragma unroll
        for (int q = 0; q < 8; q++) { C += scnt[q]; L += sl1[q]; }
        out[2 * BDn + Bn + r] = (float)C * (1.0f / 2048.0f);
        gl1[r] = L;
    }
}

// ---------------------------------------------------------------------------
// Kernel 7: deterministic mean of per-row L1 sums.
// ---------------------------------------------------------------------------
__global__ __launch_bounds__(256)
void l1_reduce_kernel(const float* __restrict__ gl1, float* __restrict__ out_l1)
{
    __shared__ double sd[256];
    const int t = threadIdx.x;
    double s = 0.0;
    for (int i = t; i < Bn; i += 256) s += (double)gl1[i];
    sd[t] = s;
    __syncthreads();
#pragma unroll
    for (int off = 128; off > 0; off >>= 1) {
        if (t < off) sd[t] += sd[t + off];
        __syncthreads();
    }
    if (t == 0) out_l1[0] = (float)(sd[0] / (double)Bn);
}

// ---------------------------------------------------------------------------
extern "C" void kernel_launch(void* const* d_in, const int* in_sizes, int n_in,
                              void* d_out, int out_size)
{
    const float* x  = (const float*)d_in[0];
    const float* W1 = (const float*)d_in[1];
    const float* b1 = (const float*)d_in[2];
    const float* W2 = (const float*)d_in[3];
    const float* b2 = (const float*)d_in[4];
    float* out = (float*)d_out;

    int* gk; float* gl1;
    cudaGetSymbolAddress((void**)&gk,  g_k);
    cudaGetSymbolAddress((void**)&gl1, g_l1);

    convert_x_kernel<<<Bn * Dn / (256 * 8), 256>>>(x);
    convert_w_kernel<<<dim3(64, 16), dim3(32, 8)>>>(W1);
    mma_gemm_kernel<<<dim3(128, 4), 256>>>(b1, W2);
    pred_final_kernel<<<Bn / 256, 256>>>(b2, out + 2 * BDn, gk);
    fixup_kernel<<<128, 512>>>(x, W1, b1, W2, b2, out + 2 * BDn, gk);
    select_kernel<<<Bn, 256>>>(x, gk, out, gl1);
    l1_reduce_kernel<<<1, 256>>>(gl1, out + 2 * BDn + 2 * (size_t)Bn);
}

// round 6
// speedup vs baseline: 1.0541x; 1.0541x over previous
#include <cuda_runtime.h>
#include <cuda_bf16.h>
#include <cstdint>

// Problem constants (fixed by the dataset)
#define Bn 16384
#define Dn 2048
#define Hn 512
#define BDn ((size_t)Bn * (size_t)Dn)

// ---------------------------------------------------------------------------
// Scratch (device globals — no allocations allowed)
// ---------------------------------------------------------------------------
__device__ __align__(16) __nv_bfloat16 g_xhi[BDn];                  // 64 MB
__device__ __align__(16) __nv_bfloat16 g_xlo[BDn];                  // 64 MB
__device__ __align__(16) __nv_bfloat16 g_w1t_hi[(size_t)Hn * Dn];  // 2 MB (W1^T [n][k])
__device__ __align__(16) __nv_bfloat16 g_w1t_lo[(size_t)Hn * Dn];
__device__ float g_part[4 * Bn];    // per-nblock row partial sums
__device__ int   g_fixcnt;
__device__ int   g_fixlist[Bn];
__device__ int   g_k[Bn];
__device__ float g_l1[Bn];

// ---------------------------------------------------------------------------
// PTX helpers — base-target instructions only (compute_103-safe).
// ---------------------------------------------------------------------------
__device__ __forceinline__ uint32_t smem_u32(const void* p) {
    uint32_t a;
    asm("{ .reg .u64 t; cvta.to.shared.u64 t, %1; cvt.u32.u64 %0, t; }" : "=r"(a) : "l"(p));
    return a;
}
__device__ __forceinline__ void cp16(uint32_t s, const void* g) {
    asm volatile("cp.async.cg.shared.global [%0], [%1], 16;" :: "r"(s), "l"(g));
}
#define CP_COMMIT() asm volatile("cp.async.commit_group;" ::: "memory")
#define CP_WAIT(n)  asm volatile("cp.async.wait_group %0;" :: "n"(n) : "memory")

#define LDSM4(r, a) \
    asm volatile("ldmatrix.sync.aligned.m8n8.x4.shared.b16 {%0,%1,%2,%3}, [%4];" \
        : "=r"((r)[0]), "=r"((r)[1]), "=r"((r)[2]), "=r"((r)[3]) : "r"(a))

__device__ __forceinline__ void mma16816(float* c, const uint32_t* a,
                                         uint32_t b0, uint32_t b1) {
    asm volatile("mma.sync.aligned.m16n8k16.row.col.f32.bf16.bf16.f32 "
        "{%0,%1,%2,%3},{%4,%5,%6,%7},{%8,%9},{%0,%1,%2,%3};"
        : "+f"(c[0]), "+f"(c[1]), "+f"(c[2]), "+f"(c[3])
        : "r"(a[0]), "r"(a[1]), "r"(a[2]), "r"(a[3]), "r"(b0), "r"(b1));
}

// ---------------------------------------------------------------------------
// Kernel 1: convert x -> (hi, lo) bf16 split. Also zeroes the fixup counter.
// ---------------------------------------------------------------------------
__global__ __launch_bounds__(256)
void convert_x_kernel(const float* __restrict__ x)
{
    if (blockIdx.x == 0 && threadIdx.x == 0) g_fixcnt = 0;
    size_t i = ((size_t)blockIdx.x * 256 + threadIdx.x) * 8;
    float4 a = *(const float4*)(x + i);
    float4 b = *(const float4*)(x + i + 4);
    float v[8] = {a.x, a.y, a.z, a.w, b.x, b.y, b.z, b.w};
    __align__(16) __nv_bfloat16 h[8], l[8];
#pragma unroll
    for (int j = 0; j < 8; j++) {
        h[j] = __float2bfloat16_rn(v[j]);
        l[j] = __float2bfloat16_rn(v[j] - __bfloat162float(h[j]));
    }
    *(uint4*)(g_xhi + i) = *(uint4*)h;
    *(uint4*)(g_xlo + i) = *(uint4*)l;
}

// ---------------------------------------------------------------------------
// Kernel 2: transpose + split W1 [K,N] f32 -> W1^T [N,K] bf16 hi/lo.
// ---------------------------------------------------------------------------
__global__ void convert_w_kernel(const float* __restrict__ W1)
{
    __shared__ float tile[32][33];
    const int kb = blockIdx.x * 32, nb = blockIdx.y * 32;
    const int tx = threadIdx.x, ty = threadIdx.y;
#pragma unroll
    for (int i = 0; i < 32; i += 8)
        tile[ty + i][tx] = W1[(size_t)(kb + ty + i) * Hn + nb + tx];
    __syncthreads();
#pragma unroll
    for (int i = 0; i < 32; i += 8) {
        const int n = nb + ty + i, k = kb + tx;
        float v = tile[tx][ty + i];
        __nv_bfloat16 h = __float2bfloat16_rn(v);
        __nv_bfloat16 l = __float2bfloat16_rn(v - __bfloat162float(h));
        g_w1t_hi[(size_t)n * Dn + k] = h;
        g_w1t_lo[(size_t)n * Dn + k] = l;
    }
}

// ---------------------------------------------------------------------------
// Kernel 3: warp-MMA bf16 GEMM, 4-stage cp.async pipeline, 1 barrier/iter.
// CTA 128(m) x 128(n); grid (128, 4); 8 warps = 2m x 4n, warp tile 64x32.
// K: 3 splits x 64 chunks of 32.  Smem row stride 80B (ldmatrix conflict-free).
// ---------------------------------------------------------------------------
#define STG   10240                 // bytes per stage per operand (128 rows * 80B)
#define NSTG  4
#define DSMEM (NSTG * STG * 2 + 2048)   // A stages + B stages + rs[128][4]

__global__ __launch_bounds__(256, 2)
void mma_gemm_kernel(const float* __restrict__ b1,
                     const float* __restrict__ W2)
{
    extern __shared__ __align__(16) char dsm[];
    const uint32_t saA = smem_u32(dsm);
    const uint32_t saB = saA + NSTG * STG;
    float (*rs)[4] = (float(*)[4])(dsm + NSTG * STG * 2);

    const int t = threadIdx.x;
    const int w = t >> 5, lane = t & 31;
    const int mb = blockIdx.x;               // 0..127
    const int nb = blockIdx.y;               // 0..3
    const int warp_m = (w >> 2) * 64;
    const int warp_n = (w & 3) * 32;

    // split source pointers (terms: hi*Whi, hi*Wlo, lo*Whi)
    const __nv_bfloat16* Aspl[3] = {
        g_xhi + (size_t)mb * 128 * Dn, g_xhi + (size_t)mb * 128 * Dn,
        g_xlo + (size_t)mb * 128 * Dn };
    const __nv_bfloat16* Bspl[3] = {
        g_w1t_hi + (size_t)nb * 128 * Dn, g_w1t_lo + (size_t)nb * 128 * Dn,
        g_w1t_hi + (size_t)nb * 128 * Dn };

    // cp.async per-thread mapping: 512 16B-chunks per operand, 2 per thread
    const int r0 = t >> 2,        c0 = t & 3;
    const int r1 = (t + 256) >> 2;
    const uint32_t oS0 = r0 * 80 + c0 * 16;
    const uint32_t oS1 = r1 * 80 + c0 * 16;
    const size_t   eG0 = (size_t)r0 * Dn + c0 * 8;
    const size_t   eG1 = (size_t)r1 * Dn + c0 * 8;

    // ldmatrix per-thread base offsets
    const uint32_t aOff = (uint32_t)(warp_m + (lane & 7) + ((lane >> 3) & 1) * 8) * 80
                        + ((lane >> 4) & 1) * 16;
    const uint32_t bOff = (uint32_t)(warp_n + (lane & 7) + ((lane >> 4) & 1) * 8) * 80
                        + ((lane >> 3) & 1) * 16;

    // epilogue constants loaded early (independent of mainloop)
    float biasv[8], w2v[8];
#pragma unroll
    for (int fn = 0; fn < 4; fn++)
#pragma unroll
        for (int e = 0; e < 2; e++) {
            const int colg = nb * 128 + warp_n + 8 * fn + 2 * (lane & 3) + e;
            biasv[fn * 2 + e] = __ldg(&b1[colg]);
            w2v[fn * 2 + e]   = __ldg(&W2[colg]);
        }

    float acc[4][4][4];
#pragma unroll
    for (int i = 0; i < 4; i++)
#pragma unroll
        for (int j = 0; j < 4; j++)
#pragma unroll
            for (int q = 0; q < 4; q++) acc[i][j][q] = 0.f;

#define ISSUE(nc) do { \
        const int _s = (nc) >> 6, _kc = (nc) & 63; \
        const __nv_bfloat16* _Ab = Aspl[_s] + _kc * 32; \
        const __nv_bfloat16* _Bb = Bspl[_s] + _kc * 32; \
        const uint32_t _so = (uint32_t)(((nc) & (NSTG - 1)) * STG); \
        cp16(saA + _so + oS0, _Ab + eG0); cp16(saA + _so + oS1, _Ab + eG1); \
        cp16(saB + _so + oS0, _Bb + eG0); cp16(saB + _so + oS1, _Bb + eG1); \
    } while (0)

    // prologue: 3 stages in flight
    ISSUE(0); CP_COMMIT();
    ISSUE(1); CP_COMMIT();
    ISSUE(2); CP_COMMIT();

    for (int cc = 0; cc < 192; cc++) {
        CP_WAIT(2);                 // one group per iter (incl. empties) -> chunk cc ready
        __syncthreads();            // all threads' stage-cc data visible; frees stage (cc-1)%4

        if (cc + 3 < 192) ISSUE(cc + 3);
        CP_COMMIT();                // unconditional: keeps group count uniform for the tail

        const uint32_t sA = saA + (uint32_t)((cc & (NSTG - 1)) * STG) + aOff;
        const uint32_t sB = saB + (uint32_t)((cc & (NSTG - 1)) * STG) + bOff;
#pragma unroll
        for (int kk = 0; kk < 2; kk++) {
            uint32_t af[4][4], bf[2][4];
#pragma unroll
            for (int fm = 0; fm < 4; fm++) LDSM4(af[fm], sA + fm * (16 * 80) + kk * 32);
#pragma unroll
            for (int fp = 0; fp < 2; fp++) LDSM4(bf[fp], sB + fp * (16 * 80) + kk * 32);
#pragma unroll
            for (int fm = 0; fm < 4; fm++)
#pragma unroll
                for (int fn = 0; fn < 4; fn++)
                    mma16816(acc[fm][fn], af[fm],
                             bf[fn >> 1][(fn & 1) * 2], bf[fn >> 1][(fn & 1) * 2 + 1]);
        }
    }
    __syncthreads();

    // ---- epilogue: relu(c + b1)*W2, reduce over this CTA's 128 n-cols ----
#pragma unroll
    for (int fm = 0; fm < 4; fm++) {
        float s0 = 0.f, s1 = 0.f;
#pragma unroll
        for (int fn = 0; fn < 4; fn++)
#pragma unroll
            for (int e = 0; e < 2; e++) {
                s0 += fmaxf(acc[fm][fn][e]     + biasv[fn * 2 + e], 0.f) * w2v[fn * 2 + e];
                s1 += fmaxf(acc[fm][fn][2 + e] + biasv[fn * 2 + e], 0.f) * w2v[fn * 2 + e];
            }
        s0 += __shfl_xor_sync(0xffffffffu, s0, 1);
        s0 += __shfl_xor_sync(0xffffffffu, s0, 2);
        s1 += __shfl_xor_sync(0xffffffffu, s1, 1);
        s1 += __shfl_xor_sync(0xffffffffu, s1, 2);
        if ((lane & 3) == 0) {
            rs[warp_m + 16 * fm + (lane >> 2)][w & 3]     = s0;
            rs[warp_m + 16 * fm + 8 + (lane >> 2)][w & 3] = s1;
        }
    }
    __syncthreads();
    if (t < 128)
        g_part[(size_t)nb * Bn + mb * 128 + t] = rs[t][0] + rs[t][1] + rs[t][2] + rs[t][3];
#undef ISSUE
}

// ---------------------------------------------------------------------------
// Kernel 4: combine 4 n-block partials -> sigmoid -> sparsity, k, fixup flags.
// ---------------------------------------------------------------------------
__global__ __launch_bounds__(256)
void pred_final_kernel(const float* __restrict__ b2,
                       float* __restrict__ out_sparsity,
                       int* __restrict__ gk)
{
    const int row = blockIdx.x * 256 + threadIdx.x;
    float s = g_part[row] + g_part[Bn + row] + g_part[2 * Bn + row] + g_part[3 * Bn + row];
    float logit = s + b2[0];
    float sig = 1.f / (1.f + expf(-logit));
    float sp  = 0.05f + 0.25f * sig;
    float kf  = 2048.f * (1.f - sp);
    int k = (int)rintf(kf);
    if (k < 1) k = 1;
    out_sparsity[row] = sp;
    gk[row] = k;
    float frac = kf - floorf(kf);
    if (fabsf(frac - 0.5f) < 0.004f) {     // bf16-split error << 0.004
        int idx = atomicAdd(&g_fixcnt, 1);
        g_fixlist[idx] = row;
    }
}

// ---------------------------------------------------------------------------
// Kernel 5: exact fp32 recompute of sparsity/k for flagged boundary rows.
// ---------------------------------------------------------------------------
__global__ __launch_bounds__(512)
void fixup_kernel(const float* __restrict__ x,
                  const float* __restrict__ W1,
                  const float* __restrict__ b1,
                  const float* __restrict__ W2,
                  const float* __restrict__ b2,
                  float* __restrict__ out_sparsity,
                  int* __restrict__ gk)
{
    __shared__ float xs[Dn];
    __shared__ float rsw[16];
    const int cnt = g_fixcnt;
    const int n = threadIdx.x;
    const int lane = n & 31, w = n >> 5;

    for (int it = blockIdx.x; it < cnt; it += gridDim.x) {
        const int r = g_fixlist[it];
        const float* xr = x + (size_t)r * Dn;
        for (int k = n; k < Dn; k += 512) xs[k] = xr[k];
        __syncthreads();

        float h = 0.f;
        for (int k = 0; k < Dn; k++) h = fmaf(xs[k], W1[(size_t)k * Hn + n], h);
        float p = fmaxf(h + b1[n], 0.f) * W2[n];
#pragma unroll
        for (int o = 16; o > 0; o >>= 1) p += __shfl_down_sync(0xffffffffu, p, o);
        if (lane == 0) rsw[w] = p;
        __syncthreads();
        if (n == 0) {
            float s = 0.f;
#pragma unroll
            for (int q = 0; q < 16; q++) s += rsw[q];
            float logit = s + b2[0];
            float sig = 1.f / (1.f + expf(-logit));
            float sp  = 0.05f + 0.25f * sig;
            int k = (int)rintf(2048.f * (1.f - sp));
            if (k < 1) k = 1;
            out_sparsity[r] = sp;
            gk[r] = k;
        }
        __syncthreads();
    }
}

// ---------------------------------------------------------------------------
// Kernel 6: per-row exact k-th smallest |x| via radix select (unchanged).
// ---------------------------------------------------------------------------
__global__ __launch_bounds__(256)
void select_kernel(const float* __restrict__ x,
                   const int* __restrict__ gk,
                   float* __restrict__ out,
                   float* __restrict__ gl1)
{
    __shared__ int hist[256];
    __shared__ int warpsum[8];
    __shared__ int warpoff[8];
    __shared__ int s_bin, s_rem;
    __shared__ int scnt[8];
    __shared__ float sl1[8];

    const int r = blockIdx.x;
    const int t = threadIdx.x;
    const float* xr = x + (size_t)r * Dn;

    float    xv[8];
    unsigned kb[8];
#pragma unroll
    for (int i = 0; i < 8; i++) {
        xv[i] = xr[t + 256 * i];
        kb[i] = __float_as_uint(fabsf(xv[i]));
    }

    int kt = gk[r];
    unsigned prefix = 0, himask = 0;

#pragma unroll
    for (int p = 3; p >= 0; p--) {
        const int shift = p * 8;
        hist[t] = 0;
        __syncthreads();

#pragma unroll
        for (int i = 0; i < 8; i++) {
            unsigned key = kb[i];
            bool act = ((key & himask) == prefix);
            int bin = act ? (int)((key >> shift) & 0xFF) : -1;
            unsigned grp = __match_any_sync(0xffffffffu, bin);
            int leader = __ffs(grp) - 1;
            if (act && (t & 31) == leader) atomicAdd(&hist[bin], __popc(grp));
        }
        __syncthreads();

        int c = hist[t];
        int v = c;
        const int lane = t & 31, w = t >> 5;
#pragma unroll
        for (int o = 1; o < 32; o <<= 1) {
            int nn = __shfl_up_sync(0xffffffffu, v, o);
            if (lane >= o) v += nn;
        }
        if (lane == 31) warpsum[w] = v;
        __syncthreads();
        if (t == 0) {
            int run = 0;
#pragma unroll
            for (int q = 0; q < 8; q++) { warpoff[q] = run; run += warpsum[q]; }
        }
        __syncthreads();
        int incl = v + warpoff[w];
        int excl = incl - c;
        if (excl < kt && incl >= kt) { s_bin = t; s_rem = kt - excl; }
        __syncthreads();

        prefix |= ((unsigned)s_bin) << shift;
        kt = s_rem;
        himask |= 0xFFu << shift;
        __syncthreads();
    }

    const unsigned thr = prefix;
    int cnt = 0;
    float l1 = 0.f;
    const size_t base = (size_t)r * Dn;
#pragma unroll
    for (int i = 0; i < 8; i++) {
        bool keep = kb[i] > thr;
        size_t idx = base + (size_t)(t + 256 * i);
        out[idx]       = keep ? xv[i] : 0.f;
        out[BDn + idx] = keep ? 1.f : 0.f;
        cnt += keep ? 1 : 0;
        l1  += keep ? __uint_as_float(kb[i]) : 0.f;
    }

    const int lane = t & 31, w = t >> 5;
#pragma unroll
    for (int o = 16; o > 0; o >>= 1) {
        cnt += __shfl_down_sync(0xffffffffu, cnt, o);
        l1  += __shfl_down_sync(0xffffffffu, l1, o);
    }
    if (lane == 0) { scnt[w] = cnt; sl1[w] = l1; }
    __syncthreads();
    if (t == 0) {
        int C = 0; float L = 0.f;
#pragma unroll
        for (int q = 0; q < 8; q++) { C += scnt[q]; L += sl1[q]; }
        out[2 * BDn + Bn + r] = (float)C * (1.0f / 2048.0f);
        gl1[r] = L;
    }
}

// ---------------------------------------------------------------------------
// Kernel 7: deterministic mean of per-row L1 sums.
// ---------------------------------------------------------------------------
__global__ __launch_bounds__(256)
void l1_reduce_kernel(const float* __restrict__ gl1, float* __restrict__ out_l1)
{
    __shared__ double sd[256];
    const int t = threadIdx.x;
    double s = 0.0;
    for (int i = t; i < Bn; i += 256) s += (double)gl1[i];
    sd[t] = s;
    __syncthreads();
#pragma unroll
    for (int off = 128; off > 0; off >>= 1) {
        if (t < off) sd[t] += sd[t + off];
        __syncthreads();
    }
    if (t == 0) out_l1[0] = (float)(sd[0] / (double)Bn);
}

// ---------------------------------------------------------------------------
extern "C" void kernel_launch(void* const* d_in, const int* in_sizes, int n_in,
                              void* d_out, int out_size)
{
    const float* x  = (const float*)d_in[0];
    const float* W1 = (const float*)d_in[1];
    const float* b1 = (const float*)d_in[2];
    const float* W2 = (const float*)d_in[3];
    const float* b2 = (const float*)d_in[4];
    float* out = (float*)d_out;

    int* gk; float* gl1;
    cudaGetSymbolAddress((void**)&gk,  g_k);
    cudaGetSymbolAddress((void**)&gl1, g_l1);

    cudaFuncSetAttribute(mma_gemm_kernel,
                         cudaFuncAttributeMaxDynamicSharedMemorySize, DSMEM);

    convert_x_kernel<<<Bn * Dn / (256 * 8), 256>>>(x);
    convert_w_kernel<<<dim3(64, 16), dim3(32, 8)>>>(W1);
    mma_gemm_kernel<<<dim3(128, 4), 256, DSMEM>>>(b1, W2);
    pred_final_kernel<<<Bn / 256, 256>>>(b2, out + 2 * BDn, gk);
    fixup_kernel<<<128, 512>>>(x, W1, b1, W2, b2, out + 2 * BDn, gk);
    select_kernel<<<Bn, 256>>>(x, gk, out, gl1);
    l1_reduce_kernel<<<1, 256>>>(gl1, out + 2 * BDn + 2 * (size_t)Bn);
}

// round 7
// speedup vs baseline: 1.1712x; 1.1111x over previous
#include <cuda_runtime.h>
#include <cuda_bf16.h>
#include <cstdint>

// Problem constants (fixed by the dataset)
#define Bn 16384
#define Dn 2048
#define Hn 512
#define BDn ((size_t)Bn * (size_t)Dn)

// ---------------------------------------------------------------------------
// Scratch (device globals — no allocations allowed)
// Tiled+swizzled operand layouts for bulk copies:
//   g_xt: [mb=128][kc=32][{hi,lo}][tile 8192 bf16]   (tile = 128 rows x 64 k)
//   g_wt: [nb=4]  [kc=32][{hi,lo}][tile 8192 bf16]
// In-tile element offset: r*64 + ((g ^ (r&7))*8) + e, g = k/8, e = k%8.
// ---------------------------------------------------------------------------
__device__ __align__(16) __nv_bfloat16 g_xt[(size_t)128 * 32 * 2 * 8192];  // 128 MB
__device__ __align__(16) __nv_bfloat16 g_wt[(size_t)4 * 32 * 2 * 8192];    // 4 MB
__device__ float g_part[4 * Bn];    // per-nblock row partial sums
__device__ int   g_fixcnt;
__device__ int   g_fixlist[Bn];
__device__ int   g_k[Bn];
__device__ float g_l1[Bn];

// ---------------------------------------------------------------------------
// PTX helpers — base-target (compute_103-safe): ldmatrix, mma, cp.async.bulk,
// mbarrier. NO tcgen05.
// ---------------------------------------------------------------------------
__device__ __forceinline__ uint32_t smem_u32(const void* p) {
    uint32_t a;
    asm("{ .reg .u64 t; cvta.to.shared.u64 t, %1; cvt.u32.u64 %0, t; }" : "=r"(a) : "l"(p));
    return a;
}
#define MBAR_INIT(a, n) asm volatile("mbarrier.init.shared.b64 [%0], %1;" :: "r"(a), "r"(n) : "memory")
#define MBAR_EXPECT(a, bytes) \
    asm volatile("mbarrier.arrive.expect_tx.shared.b64 _, [%0], %1;" :: "r"(a), "r"(bytes) : "memory")
#define MBAR_WAIT(a, p) do { \
    uint32_t _m = (a), _p = (p), _d; \
    asm volatile("{ .reg .pred q; mbarrier.try_wait.parity.acquire.cta.shared::cta.b64 q, [%1], %2; selp.b32 %0,1,0,q; }" \
                 : "=r"(_d) : "r"(_m), "r"(_p) : "memory"); \
    if (!_d) { \
        asm volatile("{ .reg .pred Q;\nWL_%=:\nmbarrier.try_wait.parity.acquire.cta.shared::cta.b64 Q, [%0], %1, 0x989680;\n@Q bra.uni WD_%=;\nbra.uni WL_%=;\nWD_%=:\n}" \
                     :: "r"(_m), "r"(_p) : "memory"); \
    } } while (0)
#define BULK_G2S(dst, src, sz, mb_) \
    asm volatile("cp.async.bulk.shared::cta.global.mbarrier::complete_tx::bytes [%0], [%1], %2, [%3];" \
                 :: "r"(dst), "l"(src), "r"(sz), "r"(mb_) : "memory")

#define LDSM4(r, a) \
    asm volatile("ldmatrix.sync.aligned.m8n8.x4.shared.b16 {%0,%1,%2,%3}, [%4];" \
        : "=r"((r)[0]), "=r"((r)[1]), "=r"((r)[2]), "=r"((r)[3]) : "r"(a))

__device__ __forceinline__ void mma16816(float* c, const uint32_t* a,
                                         uint32_t b0, uint32_t b1) {
    asm volatile("mma.sync.aligned.m16n8k16.row.col.f32.bf16.bf16.f32 "
        "{%0,%1,%2,%3},{%4,%5,%6,%7},{%8,%9},{%0,%1,%2,%3};"
        : "+f"(c[0]), "+f"(c[1]), "+f"(c[2]), "+f"(c[3])
        : "r"(a[0]), "r"(a[1]), "r"(a[2]), "r"(a[3]), "r"(b0), "r"(b1));
}

// ---------------------------------------------------------------------------
// Kernel 1: convert x -> (hi, lo) bf16 split, written TILED+SWIZZLED.
// ---------------------------------------------------------------------------
__global__ __launch_bounds__(256)
void convert_x_kernel(const float* __restrict__ x)
{
    if (blockIdx.x == 0 && threadIdx.x == 0) g_fixcnt = 0;
    size_t i = ((size_t)blockIdx.x * 256 + threadIdx.x) * 8;
    float4 a = *(const float4*)(x + i);
    float4 b = *(const float4*)(x + i + 4);
    float v[8] = {a.x, a.y, a.z, a.w, b.x, b.y, b.z, b.w};
    __align__(16) __nv_bfloat16 h[8], l[8];
#pragma unroll
    for (int j = 0; j < 8; j++) {
        h[j] = __float2bfloat16_rn(v[j]);
        l[j] = __float2bfloat16_rn(v[j] - __bfloat162float(h[j]));
    }
    const int R = (int)(i >> 11), K = (int)(i & 2047);
    const int mb = R >> 7, r = R & 127;
    const int kc = K >> 6, g = (K & 63) >> 3;
    const size_t base = ((size_t)(mb * 32 + kc) * 2) * 8192
                      + (size_t)(r * 64 + ((g ^ (r & 7)) * 8));
    *(uint4*)(g_xt + base)        = *(uint4*)h;   // hi tile
    *(uint4*)(g_xt + base + 8192) = *(uint4*)l;   // lo tile
}

// ---------------------------------------------------------------------------
// Kernel 2: transpose + split W1 [K,N] f32 -> tiled+swizzled W^T bf16 hi/lo.
// 32x32 smem tiles, block (32,8), grid (64,16).
// ---------------------------------------------------------------------------
__global__ void convert_w_kernel(const float* __restrict__ W1)
{
    __shared__ float tile[32][33];
    const int kb = blockIdx.x * 32, nb0 = blockIdx.y * 32;
    const int tx = threadIdx.x, ty = threadIdx.y;
#pragma unroll
    for (int i = 0; i < 32; i += 8)
        tile[ty + i][tx] = W1[(size_t)(kb + ty + i) * Hn + nb0 + tx];
    __syncthreads();

    const int tid = ty * 32 + tx;
    const int nn  = tid >> 3;          // n within 32-tile
    const int sub = tid & 7;           // 4 k-elems each
    const int n   = nb0 + nn;
    const int nbi = n >> 7, rr = n & 127;
    const int k0  = kb + sub * 4;
    const int kc  = k0 >> 6, g = (k0 & 63) >> 3, e = k0 & 7;

    __align__(8) __nv_bfloat16 h[4], l[4];
#pragma unroll
    for (int j = 0; j < 4; j++) {
        float v = tile[sub * 4 + j][nn];
        h[j] = __float2bfloat16_rn(v);
        l[j] = __float2bfloat16_rn(v - __bfloat162float(h[j]));
    }
    const size_t base = ((size_t)(nbi * 32 + kc) * 2) * 8192
                      + (size_t)(rr * 64 + ((g ^ (rr & 7)) * 8) + e);
    *(uint64_t*)(g_wt + base)        = *(uint64_t*)h;
    *(uint64_t*)(g_wt + base + 8192) = *(uint64_t*)l;
}

// ---------------------------------------------------------------------------
// Kernel 3: warp-MMA bf16 GEMM, cp.async.bulk + mbarrier pipeline (3 stages).
// CTA 128(m) x 128(n); grid (128, 4); 8 warps = 2m x 4n, warp tile 64x32.
// Shared-chunk scheme: per K=64 chunk load {Ahi,Alo,Bhi,Blo} once (64KB),
// run all 3 split terms (hi*Whi + hi*Wlo + lo*Whi) into one accumulator.
// ---------------------------------------------------------------------------
#define TILE_B  16384               // one operand tile: 128 x 64 bf16
#define STAGEB  (4 * TILE_B)        // Ahi|Alo|Bhi|Blo = 64KB
#define NSTG    3
#define NCHUNK  32
#define DSMEM   (NSTG * STAGEB)     // 192KB dynamic

__global__ __launch_bounds__(256, 1)
void mma_gemm_kernel(const float* __restrict__ b1,
                     const float* __restrict__ W2)
{
    extern __shared__ __align__(128) char dsm[];
    __shared__ __align__(8) unsigned long long s_mbar[NSTG];
    __shared__ float rs[128][4];

    const int t = threadIdx.x;
    const int w = t >> 5, lane = t & 31;
    const int mb = blockIdx.x;               // 0..127
    const int nb = blockIdx.y;               // 0..3
    const int warp_m = (w >> 2) * 64;
    const int warp_n = (w & 3) * 32;

    const uint32_t stage0 = smem_u32(dsm);
    uint32_t mbar[NSTG];
#pragma unroll
    for (int s = 0; s < NSTG; s++) mbar[s] = smem_u32(&s_mbar[s]);

    if (t == 0) {
#pragma unroll
        for (int s = 0; s < NSTG; s++) MBAR_INIT(mbar[s], 1);
    }
    __syncthreads();

    // gmem chunk bases
    const __nv_bfloat16* gA = g_xt + ((size_t)mb * 32) * 2 * 8192;
    const __nv_bfloat16* gB = g_wt + ((size_t)nb * 32) * 2 * 8192;

#define ISSUE(nc) do { \
        const uint32_t _st = stage0 + (uint32_t)(((nc) % NSTG) * STAGEB); \
        MBAR_EXPECT(mbar[(nc) % NSTG], (uint32_t)STAGEB); \
        BULK_G2S(_st,              gA + (size_t)(nc) * 2 * 8192, 2 * TILE_B, mbar[(nc) % NSTG]); \
        BULK_G2S(_st + 2 * TILE_B, gB + (size_t)(nc) * 2 * 8192, 2 * TILE_B, mbar[(nc) % NSTG]); \
    } while (0)

    if (t == 0) { ISSUE(0); ISSUE(1); ISSUE(2); }

    // ldmatrix per-thread row/granule components (swizzled tiles, 128B rows)
    const int rA  = (lane & 7) + ((lane >> 3) & 1) * 8;   // + warp_m + fm*16
    const int gA4 = (lane >> 4) & 1;                      // + kk*2
    const int rB  = (lane & 7) + ((lane >> 4) & 1) * 8;   // + warp_n + fp*16
    const int gB4 = (lane >> 3) & 1;
    const int rxa = (warp_m + rA) & 7;
    const int rxb = (warp_n + rB) & 7;
    const uint32_t aRow = (uint32_t)(warp_m + rA) * 128;
    const uint32_t bRow = (uint32_t)(warp_n + rB) * 128;

    // epilogue constants
    float biasv[8], w2v[8];
#pragma unroll
    for (int fn = 0; fn < 4; fn++)
#pragma unroll
        for (int e = 0; e < 2; e++) {
            const int colg = nb * 128 + warp_n + 8 * fn + 2 * (lane & 3) + e;
            biasv[fn * 2 + e] = __ldg(&b1[colg]);
            w2v[fn * 2 + e]   = __ldg(&W2[colg]);
        }

    float acc[4][4][4];
#pragma unroll
    for (int i = 0; i < 4; i++)
#pragma unroll
        for (int j = 0; j < 4; j++)
#pragma unroll
            for (int q = 0; q < 4; q++) acc[i][j][q] = 0.f;

    for (int cc = 0; cc < NCHUNK; cc++) {
        MBAR_WAIT(mbar[cc % NSTG], (cc / NSTG) & 1);
        const uint32_t st = stage0 + (uint32_t)((cc % NSTG) * STAGEB);
        const uint32_t stAhi = st, stAlo = st + TILE_B;
        const uint32_t stBhi = st + 2 * TILE_B, stBlo = st + 3 * TILE_B;

#pragma unroll
        for (int kk = 0; kk < 4; kk++) {
            const uint32_t gaOff = (uint32_t)(((kk * 2 + gA4) ^ rxa) << 4);
            const uint32_t gbOff = (uint32_t)(((kk * 2 + gB4) ^ rxb) << 4);
            uint32_t ah[4][4], al[4][4], bh[2][4], bl[2][4];
#pragma unroll
            for (int fm = 0; fm < 4; fm++) {
                LDSM4(ah[fm], stAhi + aRow + fm * 2048 + gaOff);
                LDSM4(al[fm], stAlo + aRow + fm * 2048 + gaOff);
            }
#pragma unroll
            for (int fp = 0; fp < 2; fp++) {
                LDSM4(bh[fp], stBhi + bRow + fp * 2048 + gbOff);
                LDSM4(bl[fp], stBlo + bRow + fp * 2048 + gbOff);
            }
#pragma unroll
            for (int fm = 0; fm < 4; fm++)
#pragma unroll
                for (int fn = 0; fn < 4; fn++) {
                    const int fp = fn >> 1, hb = (fn & 1) * 2;
                    mma16816(acc[fm][fn], ah[fm], bh[fp][hb], bh[fp][hb + 1]);  // hi*Whi
                    mma16816(acc[fm][fn], ah[fm], bl[fp][hb], bl[fp][hb + 1]);  // hi*Wlo
                    mma16816(acc[fm][fn], al[fm], bh[fp][hb], bh[fp][hb + 1]);  // lo*Whi
                }
        }
        __syncthreads();                       // all warps done reading stage
        if (t == 0 && cc + NSTG < NCHUNK) ISSUE(cc + NSTG);
    }

    // ---- epilogue: relu(c + b1)*W2, reduce over this CTA's 128 n-cols ----
#pragma unroll
    for (int fm = 0; fm < 4; fm++) {
        float s0 = 0.f, s1 = 0.f;
#pragma unroll
        for (int fn = 0; fn < 4; fn++)
#pragma unroll
            for (int e = 0; e < 2; e++) {
                s0 += fmaxf(acc[fm][fn][e]     + biasv[fn * 2 + e], 0.f) * w2v[fn * 2 + e];
                s1 += fmaxf(acc[fm][fn][2 + e] + biasv[fn * 2 + e], 0.f) * w2v[fn * 2 + e];
            }
        s0 += __shfl_xor_sync(0xffffffffu, s0, 1);
        s0 += __shfl_xor_sync(0xffffffffu, s0, 2);
        s1 += __shfl_xor_sync(0xffffffffu, s1, 1);
        s1 += __shfl_xor_sync(0xffffffffu, s1, 2);
        if ((lane & 3) == 0) {
            rs[warp_m + 16 * fm + (lane >> 2)][w & 3]     = s0;
            rs[warp_m + 16 * fm + 8 + (lane >> 2)][w & 3] = s1;
        }
    }
    __syncthreads();
    if (t < 128)
        g_part[(size_t)nb * Bn + mb * 128 + t] = rs[t][0] + rs[t][1] + rs[t][2] + rs[t][3];
#undef ISSUE
}

// ---------------------------------------------------------------------------
// Kernel 4: combine 4 n-block partials -> sigmoid -> sparsity, k, fixup flags.
// ---------------------------------------------------------------------------
__global__ __launch_bounds__(256)
void pred_final_kernel(const float* __restrict__ b2,
                       float* __restrict__ out_sparsity,
                       int* __restrict__ gk)
{
    const int row = blockIdx.x * 256 + threadIdx.x;
    float s = g_part[row] + g_part[Bn + row] + g_part[2 * Bn + row] + g_part[3 * Bn + row];
    float logit = s + b2[0];
    float sig = 1.f / (1.f + expf(-logit));
    float sp  = 0.05f + 0.25f * sig;
    float kf  = 2048.f * (1.f - sp);
    int k = (int)rintf(kf);
    if (k < 1) k = 1;
    out_sparsity[row] = sp;
    gk[row] = k;
    float frac = kf - floorf(kf);
    if (fabsf(frac - 0.5f) < 0.004f) {     // bf16-split error << 0.004
        int idx = atomicAdd(&g_fixcnt, 1);
        g_fixlist[idx] = row;
    }
}

// ---------------------------------------------------------------------------
// Kernel 5: exact fp32 recompute of sparsity/k for flagged boundary rows.
// ---------------------------------------------------------------------------
__global__ __launch_bounds__(512)
void fixup_kernel(const float* __restrict__ x,
                  const float* __restrict__ W1,
                  const float* __restrict__ b1,
                  const float* __restrict__ W2,
                  const float* __restrict__ b2,
                  float* __restrict__ out_sparsity,
                  int* __restrict__ gk)
{
    __shared__ float xs[Dn];
    __shared__ float rsw[16];
    const int cnt = g_fixcnt;
    const int n = threadIdx.x;
    const int lane = n & 31, w = n >> 5;

    for (int it = blockIdx.x; it < cnt; it += gridDim.x) {
        const int r = g_fixlist[it];
        const float* xr = x + (size_t)r * Dn;
        for (int k = n; k < Dn; k += 512) xs[k] = xr[k];
        __syncthreads();

        float h = 0.f;
        for (int k = 0; k < Dn; k++) h = fmaf(xs[k], W1[(size_t)k * Hn + n], h);
        float p = fmaxf(h + b1[n], 0.f) * W2[n];
#pragma unroll
        for (int o = 16; o > 0; o >>= 1) p += __shfl_down_sync(0xffffffffu, p, o);
        if (lane == 0) rsw[w] = p;
        __syncthreads();
        if (n == 0) {
            float s = 0.f;
#pragma unroll
            for (int q = 0; q < 16; q++) s += rsw[q];
            float logit = s + b2[0];
            float sig = 1.f / (1.f + expf(-logit));
            float sp  = 0.05f + 0.25f * sig;
            int k = (int)rintf(2048.f * (1.f - sp));
            if (k < 1) k = 1;
            out_sparsity[r] = sp;
            gk[r] = k;
        }
        __syncthreads();
    }
}

// ---------------------------------------------------------------------------
// Kernel 6: per-row exact k-th smallest |x| via radix select (unchanged).
// ---------------------------------------------------------------------------
__global__ __launch_bounds__(256)
void select_kernel(const float* __restrict__ x,
                   const int* __restrict__ gk,
                   float* __restrict__ out,
                   float* __restrict__ gl1)
{
    __shared__ int hist[256];
    __shared__ int warpsum[8];
    __shared__ int warpoff[8];
    __shared__ int s_bin, s_rem;
    __shared__ int scnt[8];
    __shared__ float sl1[8];

    const int r = blockIdx.x;
    const int t = threadIdx.x;
    const float* xr = x + (size_t)r * Dn;

    float    xv[8];
    unsigned kb[8];
#pragma unroll
    for (int i = 0; i < 8; i++) {
        xv[i] = xr[t + 256 * i];
        kb[i] = __float_as_uint(fabsf(xv[i]));
    }

    int kt = gk[r];
    unsigned prefix = 0, himask = 0;

#pragma unroll
    for (int p = 3; p >= 0; p--) {
        const int shift = p * 8;
        hist[t] = 0;
        __syncthreads();

#pragma unroll
        for (int i = 0; i < 8; i++) {
            unsigned key = kb[i];
            bool act = ((key & himask) == prefix);
            int bin = act ? (int)((key >> shift) & 0xFF) : -1;
            unsigned grp = __match_any_sync(0xffffffffu, bin);
            int leader = __ffs(grp) - 1;
            if (act && (t & 31) == leader) atomicAdd(&hist[bin], __popc(grp));
        }
        __syncthreads();

        int c = hist[t];
        int v = c;
        const int lane = t & 31, w = t >> 5;
#pragma unroll
        for (int o = 1; o < 32; o <<= 1) {
            int nn = __shfl_up_sync(0xffffffffu, v, o);
            if (lane >= o) v += nn;
        }
        if (lane == 31) warpsum[w] = v;
        __syncthreads();
        if (t == 0) {
            int run = 0;
#pragma unroll
            for (int q = 0; q < 8; q++) { warpoff[q] = run; run += warpsum[q]; }
        }
        __syncthreads();
        int incl = v + warpoff[w];
        int excl = incl - c;
        if (excl < kt && incl >= kt) { s_bin = t; s_rem = kt - excl; }
        __syncthreads();

        prefix |= ((unsigned)s_bin) << shift;
        kt = s_rem;
        himask |= 0xFFu << shift;
        __syncthreads();
    }

    const unsigned thr = prefix;
    int cnt = 0;
    float l1 = 0.f;
    const size_t base = (size_t)r * Dn;
#pragma unroll
    for (int i = 0; i < 8; i++) {
        bool keep = kb[i] > thr;
        size_t idx = base + (size_t)(t + 256 * i);
        out[idx]       = keep ? xv[i] : 0.f;
        out[BDn + idx] = keep ? 1.f : 0.f;
        cnt += keep ? 1 : 0;
        l1  += keep ? __uint_as_float(kb[i]) : 0.f;
    }

    const int lane = t & 31, w = t >> 5;
#pragma unroll
    for (int o = 16; o > 0; o >>= 1) {
        cnt += __shfl_down_sync(0xffffffffu, cnt, o);
        l1  += __shfl_down_sync(0xffffffffu, l1, o);
    }
    if (lane == 0) { scnt[w] = cnt; sl1[w] = l1; }
    __syncthreads();
    if (t == 0) {
        int C = 0; float L = 0.f;
#pragma unroll
        for (int q = 0; q < 8; q++) { C += scnt[q]; L += sl1[q]; }
        out[2 * BDn + Bn + r] = (float)C * (1.0f / 2048.0f);
        gl1[r] = L;
    }
}

// ---------------------------------------------------------------------------
// Kernel 7: deterministic mean of per-row L1 sums.
// ---------------------------------------------------------------------------
__global__ __launch_bounds__(256)
void l1_reduce_kernel(const float* __restrict__ gl1, float* __restrict__ out_l1)
{
    __shared__ double sd[256];
    const int t = threadIdx.x;
    double s = 0.0;
    for (int i = t; i < Bn; i += 256) s += (double)gl1[i];
    sd[t] = s;
    __syncthreads();
#pragma unroll
    for (int off = 128; off > 0; off >>= 1) {
        if (t < off) sd[t] += sd[t + off];
        __syncthreads();
    }
    if (t == 0) out_l1[0] = (float)(sd[0] / (double)Bn);
}

// ---------------------------------------------------------------------------
extern "C" void kernel_launch(void* const* d_in, const int* in_sizes, int n_in,
                              void* d_out, int out_size)
{
    const float* x  = (const float*)d_in[0];
    const float* W1 = (const float*)d_in[1];
    const float* b1 = (const float*)d_in[2];
    const float* W2 = (const float*)d_in[3];
    const float* b2 = (const float*)d_in[4];
    float* out = (float*)d_out;

    int* gk; float* gl1;
    cudaGetSymbolAddress((void**)&gk,  g_k);
    cudaGetSymbolAddress((void**)&gl1, g_l1);

    cudaFuncSetAttribute(mma_gemm_kernel,
                         cudaFuncAttributeMaxDynamicSharedMemorySize, DSMEM);

    convert_x_kernel<<<Bn * Dn / (256 * 8), 256>>>(x);
    convert_w_kernel<<<dim3(64, 16), dim3(32, 8)>>>(W1);
    mma_gemm_kernel<<<dim3(128, 4), 256, DSMEM>>>(b1, W2);
    pred_final_kernel<<<Bn / 256, 256>>>(b2, out + 2 * BDn, gk);
    fixup_kernel<<<128, 512>>>(x, W1, b1, W2, b2, out + 2 * BDn, gk);
    select_kernel<<<Bn, 256>>>(x, gk, out, gl1);
    l1_reduce_kernel<<<1, 256>>>(gl1, out + 2 * BDn + 2 * (size_t)Bn);
}